// round 15
// baseline (speedup 1.0000x reference)
#include <cuda_runtime.h>

// MVGeometricProduct — instruction-diet round.
// R14 (14.4us): occ/issue up but dur flat -> instruction-count wall (~350 instr/site
// vs ~160 needed). Cuts: (1) explicit products + sign folded into FFMA operand
// negation (was possibly 33 extra FMULs), (2) rsqrtf instead of __fsqrt_rn,
// (3) pointer strides instead of per-iter 64-bit site math.
// Structure unchanged: MINB=3, one-site pipeline, grid (3,148), ~7 sites/thread.

#define NR 256
#define PADW 21

__device__ __forceinline__ void normalize8(const float* ww,
                                           float s0, float s1, float s2, float s3,
                                           float* wn) {
    float sq1 = fmaf(ww[1], ww[1], fmaf(ww[2], ww[2], ww[3]*ww[3]));
    float sq2 = fmaf(ww[4], ww[4], fmaf(ww[5], ww[5], ww[6]*ww[6]));
    float nrm0 = fabsf(ww[0]);
    float nrm1 = sq1 * rsqrtf(fmaxf(sq1, 1e-30f));   // MUFU.RSQ + FMUL (vs ~8-instr sqrt_rn)
    float nrm2 = sq2 * rsqrtf(fmaxf(sq2, 1e-30f));
    float nrm3 = fabsf(ww[7]);
    float r0 = __fdividef(1.0f, fmaf(s0, nrm0 - 1.0f, 1.0f));
    float r1 = __fdividef(1.0f, fmaf(s1, nrm1 - 1.0f, 1.0f));
    float r2 = __fdividef(1.0f, fmaf(s2, nrm2 - 1.0f, 1.0f));
    float r3 = __fdividef(1.0f, fmaf(s3, nrm3 - 1.0f, 1.0f));
    wn[0] = ww[0] * r0;
    wn[1] = ww[1] * r1;  wn[2] = ww[2] * r1;  wn[3] = ww[3] * r1;
    wn[4] = ww[4] * r2;  wn[5] = ww[5] * r2;  wn[6] = ww[6] * r2;
    wn[7] = ww[7] * r3;
}

// Sign lives on the wn operand: FFMA supports free operand negation in SASS.
#define AP(J, PR, K) o[J] = fmaf(PR,  wn[K], o[J]);
#define AN(J, PR, K) o[J] = fmaf(PR, -wn[K], o[J]);

__device__ __forceinline__ void site_compute(const float* vi, const float* wn,
                                             const float* wt, float* o) {
#pragma unroll
    for (int t = 0; t < 8; ++t) o[t] = 0.0f;

    // i = 0 (scalar): 4 products
    {
        float q0 = wt[0]*vi[0], q1 = wt[1]*vi[0], q2 = wt[2]*vi[0], q3 = wt[3]*vi[0];
        AP(0,q0,0) AP(1,q1,1) AP(2,q1,2) AP(3,q1,3)
        AP(4,q2,4) AP(5,q2,5) AP(6,q2,6) AP(7,q3,7)
    }
    // i = 1 (e1): 6 products
    {
        float q4 = wt[4]*vi[1], q5 = wt[5]*vi[1], q6 = wt[6]*vi[1],
              q7 = wt[7]*vi[1], q8 = wt[8]*vi[1], q9 = wt[9]*vi[1];
        AP(1,q5,0) AP(0,q4,1) AP(4,q7,2) AP(5,q7,3)
        AP(2,q6,4) AP(3,q6,5) AP(7,q9,6) AP(6,q8,7)
    }
    // i = 2 (e2)
    {
        float q4 = wt[4]*vi[2], q5 = wt[5]*vi[2], q6 = wt[6]*vi[2],
              q7 = wt[7]*vi[2], q8 = wt[8]*vi[2], q9 = wt[9]*vi[2];
        AP(2,q5,0) AN(4,q7,1) AP(0,q4,2) AP(6,q7,3)
        AN(1,q6,4) AN(7,q9,5) AP(3,q6,6) AN(5,q8,7)
    }
    // i = 3 (e3)
    {
        float q4 = wt[4]*vi[3], q5 = wt[5]*vi[3], q6 = wt[6]*vi[3],
              q7 = wt[7]*vi[3], q8 = wt[8]*vi[3], q9 = wt[9]*vi[3];
        AP(3,q5,0) AN(5,q7,1) AN(6,q7,2) AP(0,q4,3)
        AP(7,q9,4) AN(1,q6,5) AN(2,q6,6) AP(4,q8,7)
    }
    // i = 4 (e12): 6 products
    {
        float qa = wt[10]*vi[4], qb = wt[11]*vi[4], qc = wt[12]*vi[4],
              qd = wt[13]*vi[4], qe = wt[14]*vi[4], qf = wt[15]*vi[4];
        AN(4,qd,0) AP(2,qb,1) AN(1,qb,2) AN(7,qf,3)
        AP(0,qa,4) AP(6,qe,5) AN(5,qe,6) AP(3,qc,7)
    }
    // i = 5 (e13)
    {
        float qa = wt[10]*vi[5], qb = wt[11]*vi[5], qc = wt[12]*vi[5],
              qd = wt[13]*vi[5], qe = wt[14]*vi[5], qf = wt[15]*vi[5];
        AN(5,qd,0) AP(3,qb,1) AP(7,qf,2) AN(1,qb,3)
        AN(6,qe,4) AP(0,qa,5) AP(4,qe,6) AN(2,qc,7)
    }
    // i = 6 (e23)
    {
        float qa = wt[10]*vi[6], qb = wt[11]*vi[6], qc = wt[12]*vi[6],
              qd = wt[13]*vi[6], qe = wt[14]*vi[6], qf = wt[15]*vi[6];
        AN(6,qd,0) AN(7,qf,1) AP(3,qb,2) AN(2,qb,3)
        AP(5,qe,4) AN(4,qe,5) AP(0,qa,6) AP(1,qc,7)
    }
    // i = 7 (e123): 4 products
    {
        float qg = wt[16]*vi[7], qh = wt[17]*vi[7], qi = wt[18]*vi[7], qj = wt[19]*vi[7];
        AN(7,qj,0) AN(6,qi,1) AP(5,qi,2) AN(4,qi,3)
        AP(3,qh,4) AN(2,qh,5) AP(1,qh,6) AP(0,qg,7)
    }
}

__global__ __launch_bounds__(NR, 3) void mv_gp_kernel(
    const float* __restrict__ v,
    const float* __restrict__ w,
    const float* __restrict__ weight,
    const float* __restrict__ a,
    float* __restrict__ out,
    int B, int F, int GY)
{
    __shared__ float wt_s[NR * PADW];   // row-major, padded (gcd(21,32)=1)

    const int tid = threadIdx.x;
    const int n0  = blockIdx.x * NR;

    // ---- stage weight rows: coalesced float4 reads, scalar padded writes ----
    {
        const float4* wsrc = (const float4*)(weight + (size_t)n0 * 20);
#pragma unroll
        for (int it = 0; it < 5; ++it) {
            int i = tid + it * NR;          // 1280 float4 total
            float4 x = wsrc[i];
            int e = i * 4;
            int base = (e / 20) * PADW + (e % 20);
            wt_s[base + 0] = x.x;
            wt_s[base + 1] = x.y;
            wt_s[base + 2] = x.z;
            wt_s[base + 3] = x.w;
        }
    }

    const int n = n0 + tid;

    // sigmoid(a[n]) — once per thread
    const float4 a4 = *(const float4*)(a + (size_t)n * 4);
    const float s0 = __fdividef(1.0f, 1.0f + __expf(-a4.x));
    const float s1 = __fdividef(1.0f, 1.0f + __expf(-a4.y));
    const float s2 = __fdividef(1.0f, 1.0f + __expf(-a4.z));
    const float s3 = __fdividef(1.0f, 1.0f + __expf(-a4.w));

    __syncthreads();

    // per-thread weight row (conflict-free: stride 21) — once per thread
    float wt[20];
    const float* wrow = &wt_s[tid * PADW];
#pragma unroll
    for (int p = 0; p < 20; ++p) wt[p] = wrow[p];

    const int b = blockIdx.y;
    if (b >= B) return;

    // trip count and constant pointer strides (float4 units)
    const int trips = 1 + (B - 1 - b) / GY;
    const ptrdiff_t step = (ptrdiff_t)GY * F * 2;   // GY*F sites * 8 floats / 4

    const size_t site0 = (size_t)b * F + n;
    const float4* pv = (const float4*)(v + site0 * 8);
    const float4* pw = (const float4*)(w + site0 * 8);
    float4*       po = (float4*)(out + site0 * 8);

    // ---- prologue: load first site ----
    float4 cv0 = pv[0], cv1 = pv[1];
    float4 cw0 = pw[0], cw1 = pw[1];

    // ---- pipelined loop: one site per iteration ----
    for (int t = trips - 1; ; --t) {
        float4 nv0, nv1, nw0, nw1;
        if (t > 0) {
            pv += step; pw += step;
            nv0 = pv[0]; nv1 = pv[1];
            nw0 = pw[0]; nw1 = pw[1];
        }

        // compute + store current site
        {
            float vi[8] = {cv0.x, cv0.y, cv0.z, cv0.w, cv1.x, cv1.y, cv1.z, cv1.w};
            float ww[8] = {cw0.x, cw0.y, cw0.z, cw0.w, cw1.x, cw1.y, cw1.z, cw1.w};
            float wn[8], o[8];
            normalize8(ww, s0, s1, s2, s3, wn);
            site_compute(vi, wn, wt, o);
            po[0] = make_float4(o[0], o[1], o[2], o[3]);
            po[1] = make_float4(o[4], o[5], o[6], o[7]);
        }

        if (t <= 0) break;

        po += step;
        cv0 = nv0; cv1 = nv1; cw0 = nw0; cw1 = nw1;
    }
}

extern "C" void kernel_launch(void* const* d_in, const int* in_sizes, int n_in,
                              void* d_out, int out_size) {
    const float* v      = (const float*)d_in[0];
    const float* w      = (const float*)d_in[1];
    const float* weight = (const float*)d_in[2];
    const float* a      = (const float*)d_in[3];
    float* out = (float*)d_out;

    int F     = in_sizes[3] / 4;        // a is [F, 4]
    int total = in_sizes[0] / 8;        // B * F
    int B     = total / F;

    int gx = F / NR;                    // 3
    // one wave at 3 blocks/SM: 148*3 / gx
    int gy = (148 * 3) / (gx > 0 ? gx : 1);
    if (gy > B) gy = B;
    if (gy < 1) gy = 1;

    dim3 grid(gx, gy);
    mv_gp_kernel<<<grid, NR>>>(v, w, weight, a, out, B, F, gy);
}